// round 1
// baseline (speedup 1.0000x reference)
#include <cuda_runtime.h>
#include <cuda_bf16.h>

// Problem constants (fixed-shape problem)
#define NN 100000
#define EE 3200000
#define IND 81
#define HID 64
#define LAT 32
#define BN_EPS 1e-5f

// Scratch (device globals; no allocation allowed)
__device__ float g_bufA[NN * HID];
__device__ float g_bufB[NN * HID];
__device__ float g_dis[NN];          // degree, then rsqrt(degree)
__device__ int   g_edges[2 * EE];    // src[E], dst[E] as int32
__device__ float g_stats[128];       // sum[64], sumsq[64] -> scale[64], shift[64]

// ---------------------------------------------------------------------------
// Edge index conversion: handles int64 (expected) or int32 payloads.
__global__ void convert_edges(const void* ei, int* out, int n2E) {
    int i = blockIdx.x * blockDim.x + threadIdx.x;
    if (i >= n2E) return;
    const long long* p64 = (const long long*)ei;
    long long v0 = p64[0];
    bool is64 = (v0 >= 0 && v0 < 1000000LL);   // int64 indices are small; int32-pair reinterp is ~2^32
    out[i] = is64 ? (int)p64[i] : ((const int*)ei)[i];
}

// ---------------------------------------------------------------------------
// Degree / normalization
__global__ void deg_init(float* deg, int n) {
    int i = blockIdx.x * blockDim.x + threadIdx.x;
    if (i < n) deg[i] = 1.0f;   // self-loop
}

__global__ void deg_accum(const int* __restrict__ dst, float* deg, int E) {
    int e = blockIdx.x * blockDim.x + threadIdx.x;
    if (e < E) atomicAdd(&deg[dst[e]], 1.0f);
}

__global__ void deg_rsqrt(float* deg, int n) {
    int i = blockIdx.x * blockDim.x + threadIdx.x;
    if (i < n) deg[i] = rsqrtf(deg[i]);   // deg >= 1 always (self-loops)
}

// ---------------------------------------------------------------------------
// GEMM: Y[N,64] = X[N,81] @ W[81,64]
__global__ void gemm81(const float* __restrict__ X, const float* __restrict__ W,
                       float* __restrict__ Y, int N) {
    __shared__ float Ws[IND * HID];
    __shared__ float Xs[4][IND];
    int tx = threadIdx.x;          // 0..63 (feature)
    int ty = threadIdx.y;          // 0..3  (node within group)
    int tid = ty * 64 + tx;
    for (int i = tid; i < IND * HID; i += 256) Ws[i] = W[i];
    int base = blockIdx.x * 16;
    for (int g = 0; g < 4; ++g) {
        int n0 = base + g * 4;
        __syncthreads();
        for (int i = tid; i < 4 * IND; i += 256) {
            int r = i / IND, c = i % IND;
            int n = n0 + r;
            Xs[r][c] = (n < N) ? X[n * IND + c] : 0.0f;
        }
        __syncthreads();
        int n = n0 + ty;
        if (n < N) {
            float acc = 0.0f;
            #pragma unroll
            for (int k = 0; k < IND; ++k) acc += Xs[ty][k] * Ws[k * HID + tx];
            Y[n * HID + tx] = acc;
        }
    }
}

// GEMM: Y[N,64] = X[N,64] @ W[64,64]
__global__ void gemm64(const float* __restrict__ X, const float* __restrict__ W,
                       float* __restrict__ Y, int N) {
    __shared__ float Ws[HID * HID];
    __shared__ float Xs[4][HID];
    int tx = threadIdx.x;
    int ty = threadIdx.y;
    int tid = ty * 64 + tx;
    for (int i = tid; i < HID * HID; i += 256) Ws[i] = W[i];
    int base = blockIdx.x * 16;
    for (int g = 0; g < 4; ++g) {
        int n0 = base + g * 4;
        __syncthreads();
        for (int i = tid; i < 4 * HID; i += 256) {
            int r = i >> 6, c = i & 63;
            int n = n0 + r;
            Xs[r][c] = (n < N) ? X[n * HID + c] : 0.0f;
        }
        __syncthreads();
        int n = n0 + ty;
        if (n < N) {
            float acc = 0.0f;
            #pragma unroll
            for (int k = 0; k < HID; ++k) acc += Xs[ty][k] * Ws[k * HID + tx];
            Y[n * HID + tx] = acc;
        }
    }
}

// Final: mu = agg@Wmu + bmu -> out[0 : N*32),  ls = agg@Wls + bls -> out[N*32 : 2*N*32)
__global__ void gemm_mu_ls(const float* __restrict__ X,
                           const float* __restrict__ Wmu, const float* __restrict__ bmu,
                           const float* __restrict__ Wls, const float* __restrict__ bls,
                           float* __restrict__ out, int N) {
    __shared__ float Ws[HID * 64];   // col<32 -> Wmu, col>=32 -> Wls
    __shared__ float bs[64];
    __shared__ float Xs[4][HID];
    int tx = threadIdx.x;
    int ty = threadIdx.y;
    int tid = ty * 64 + tx;
    for (int i = tid; i < HID * 64; i += 256) {
        int k = i >> 6, f = i & 63;
        Ws[i] = (f < LAT) ? Wmu[k * LAT + f] : Wls[k * LAT + (f - LAT)];
    }
    if (tid < 64) bs[tid] = (tid < LAT) ? bmu[tid] : bls[tid - LAT];
    int base = blockIdx.x * 16;
    for (int g = 0; g < 4; ++g) {
        int n0 = base + g * 4;
        __syncthreads();
        for (int i = tid; i < 4 * HID; i += 256) {
            int r = i >> 6, c = i & 63;
            int n = n0 + r;
            Xs[r][c] = (n < N) ? X[n * HID + c] : 0.0f;
        }
        __syncthreads();
        int n = n0 + ty;
        if (n < N) {
            float acc = 0.0f;
            #pragma unroll
            for (int k = 0; k < HID; ++k) acc += Xs[ty][k] * Ws[k * 64 + tx];
            int f = tx & (LAT - 1);
            long long off = (tx < LAT) ? 0 : (long long)N * LAT;
            out[off + (long long)n * LAT + f] = acc + bs[tx];
        }
    }
}

// ---------------------------------------------------------------------------
// Self-loop init (+ bias): out[n,f] = H[n,f] * dis[n]^2 + (b ? b[f] : 0)
__global__ void self_init(const float* __restrict__ H, const float* __restrict__ dis,
                          const float* __restrict__ b, float* __restrict__ out, int total) {
    int idx = blockIdx.x * blockDim.x + threadIdx.x;
    if (idx >= total) return;
    int n = idx >> 6;
    int f = idx & 63;
    float dd = dis[n];
    float bias = b ? b[f] : 0.0f;
    out[idx] = H[idx] * dd * dd + bias;
}

// Edge propagation: out[dst] += H[src] * dis[src]*dis[dst], atomics
__global__ void edge_prop(const int* __restrict__ src, const int* __restrict__ dst,
                          const float* __restrict__ dis, const float* __restrict__ H,
                          float* __restrict__ out, int total /* E*64 */) {
    int idx = blockIdx.x * blockDim.x + threadIdx.x;
    if (idx >= total) return;
    int e = idx >> 6;
    int f = idx & 63;
    int s = src[e];
    int d = dst[e];
    float w = dis[s] * dis[d];
    atomicAdd(&out[d * HID + f], H[s * HID + f] * w);
}

// ---------------------------------------------------------------------------
// BatchNorm
__global__ void zero_stats(float* stats) {
    int i = threadIdx.x;
    if (i < 128) stats[i] = 0.0f;
}

__global__ void bn_stats(const float* __restrict__ H, float* stats, int N) {
    int tid = threadIdx.x;         // 256 threads
    int col = tid & 63;
    int rlocal = tid >> 6;         // 0..3
    int r = blockIdx.x * 4 + rlocal;
    int rstride = gridDim.x * 4;
    float s = 0.0f, q = 0.0f;
    for (; r < N; r += rstride) {
        float v = H[r * HID + col];
        s += v;
        q += v * v;
    }
    __shared__ float sh[256], qh[256];
    sh[tid] = s; qh[tid] = q;
    __syncthreads();
    if (tid < 64) {
        float S = sh[tid] + sh[tid + 64] + sh[tid + 128] + sh[tid + 192];
        float Q = qh[tid] + qh[tid + 64] + qh[tid + 128] + qh[tid + 192];
        atomicAdd(&stats[tid], S);
        atomicAdd(&stats[64 + tid], Q);
    }
}

__global__ void bn_finalize(float* stats, const float* __restrict__ g,
                            const float* __restrict__ beta, int N) {
    int f = threadIdx.x;
    if (f >= 64) return;
    float invN = 1.0f / (float)N;
    float m = stats[f] * invN;
    float v = stats[64 + f] * invN - m * m;
    float scale = g[f] * rsqrtf(v + BN_EPS);
    float shift = beta[f] - m * scale;
    stats[f] = scale;
    stats[64 + f] = shift;
}

__global__ void bn_apply_relu(const float* __restrict__ H, const float* __restrict__ stats,
                              float* __restrict__ out, int total) {
    int idx = blockIdx.x * blockDim.x + threadIdx.x;
    if (idx >= total) return;
    int f = idx & 63;
    float y = fmaf(H[idx], stats[f], stats[64 + f]);
    out[idx] = fmaxf(y, 0.0f);
}

// ---------------------------------------------------------------------------
extern "C" void kernel_launch(void* const* d_in, const int* in_sizes, int n_in,
                              void* d_out, int out_size) {
    const float* x    = (const float*)d_in[0];
    const void*  ei   = d_in[1];
    const float* W1   = (const float*)d_in[2];
    const float* b1   = (const float*)d_in[3];
    const float* g1   = (const float*)d_in[4];
    const float* be1  = (const float*)d_in[5];
    const float* W2   = (const float*)d_in[6];
    const float* b2   = (const float*)d_in[7];
    const float* g2   = (const float*)d_in[8];
    const float* be2  = (const float*)d_in[9];
    const float* Wmu  = (const float*)d_in[10];
    const float* bmu  = (const float*)d_in[11];
    const float* Wls  = (const float*)d_in[12];
    const float* bls  = (const float*)d_in[13];
    float* out = (float*)d_out;

    int N = in_sizes[0] / IND;       // 100000
    int E = in_sizes[1] / 2;         // 3200000

    float *pA, *pB, *pDis, *pStats;
    int *pE;
    cudaGetSymbolAddress((void**)&pA, g_bufA);
    cudaGetSymbolAddress((void**)&pB, g_bufB);
    cudaGetSymbolAddress((void**)&pDis, g_dis);
    cudaGetSymbolAddress((void**)&pStats, g_stats);
    cudaGetSymbolAddress((void**)&pE, g_edges);
    int* pSrc = pE;
    int* pDst = pE + E;

    int NH = N * HID;
    int EH = E * HID;
    dim3 gThr(64, 4);
    int gemmGrid = (N + 15) / 16;

    // 1. edge conversion + degree norm
    convert_edges<<<(2 * E + 255) / 256, 256>>>(ei, pE, 2 * E);
    deg_init<<<(N + 255) / 256, 256>>>(pDis, N);
    deg_accum<<<(E + 255) / 256, 256>>>(pDst, pDis, E);
    deg_rsqrt<<<(N + 255) / 256, 256>>>(pDis, N);

    // 2. conv1: A = x@W1 ; B = A@A_norm + b1
    gemm81<<<gemmGrid, gThr>>>(x, W1, pA, N);
    self_init<<<(NH + 255) / 256, 256>>>(pA, pDis, b1, pB, NH);
    edge_prop<<<(EH + 255) / 256, 256>>>(pSrc, pDst, pDis, pA, pB, EH);

    // 3. BN1 + ReLU: A = relu(bn(B))
    zero_stats<<<1, 128>>>(pStats);
    bn_stats<<<512, 256>>>(pB, pStats, N);
    bn_finalize<<<1, 64>>>(pStats, g1, be1, N);
    bn_apply_relu<<<(NH + 255) / 256, 256>>>(pB, pStats, pA, NH);

    // 4. conv2: B = A@W2 ; A = prop(B) + b2
    gemm64<<<gemmGrid, gThr>>>(pA, W2, pB, N);
    self_init<<<(NH + 255) / 256, 256>>>(pB, pDis, b2, pA, NH);
    edge_prop<<<(EH + 255) / 256, 256>>>(pSrc, pDst, pDis, pB, pA, EH);

    // 5. BN2 + ReLU: B = relu(bn(A))
    zero_stats<<<1, 128>>>(pStats);
    bn_stats<<<512, 256>>>(pA, pStats, N);
    bn_finalize<<<1, 64>>>(pStats, g2, be2, N);
    bn_apply_relu<<<(NH + 255) / 256, 256>>>(pA, pStats, pB, NH);

    // 6. shared aggregation: A = A_norm @ B   (no bias)
    self_init<<<(NH + 255) / 256, 256>>>(pB, pDis, (const float*)nullptr, pA, NH);
    edge_prop<<<(EH + 255) / 256, 256>>>(pSrc, pDst, pDis, pB, pA, EH);

    // 7. heads: mu = A@Wmu + bmu, ls = A@Wls + bls
    gemm_mu_ls<<<gemmGrid, gThr>>>(pA, Wmu, bmu, Wls, bls, out, N);
}

// round 2
// speedup vs baseline: 4.3645x; 4.3645x over previous
#include <cuda_runtime.h>
#include <cuda_bf16.h>

#define NN 100000
#define EE 3200000
#define IND 81
#define HID 64
#define LAT 32
#define BN_EPS 1e-5f
#define SCAN_BLK 1024

// Scratch (device globals; no allocation allowed)
__device__ float g_bufA[NN * HID];
__device__ float g_bufB[NN * HID];
__device__ float g_dis[NN];
__device__ int   g_cnt[NN];
__device__ int   g_rowptr[NN + 1];
__device__ int   g_cursor[NN + 1];
__device__ int   g_csr[EE];
__device__ int   g_bsums[(NN + SCAN_BLK - 1) / SCAN_BLK + 1];
__device__ float g_stats[128];   // sum[64], sumsq[64] -> scale[64], shift[64]

// ---------------------------------------------------------------------------
__device__ __forceinline__ bool edges_are_i64(const void* ei) {
    long long v0 = ((const long long*)ei)[0];
    return (v0 >= 0 && v0 < 1000000LL);
}
__device__ __forceinline__ int edge_at(const void* ei, bool is64, int i) {
    return is64 ? (int)((const long long*)ei)[i] : ((const int*)ei)[i];
}

// ---------------------------------------------------------------------------
__global__ void zero_cnt(int* cnt, int n) {
    int i = blockIdx.x * blockDim.x + threadIdx.x;
    if (i < n) cnt[i] = 0;
}

__global__ void hist_dst(const void* ei, int* cnt, int E) {
    int e = blockIdx.x * blockDim.x + threadIdx.x;
    if (e >= E) return;
    bool is64 = edges_are_i64(ei);
    int d = edge_at(ei, is64, E + e);
    atomicAdd(&cnt[d], 1);
}

__global__ void dis_from_cnt(const int* __restrict__ cnt, float* __restrict__ dis, int n) {
    int i = blockIdx.x * blockDim.x + threadIdx.x;
    if (i < n) dis[i] = rsqrtf((float)(cnt[i] + 1));
}

// scan step 1: per-block inclusive scan of cnt, write rowptr[i+1], block sums
__global__ void scan1(const int* __restrict__ cnt, int* __restrict__ rowptr,
                      int* __restrict__ bsums, int n) {
    __shared__ int s[SCAN_BLK];
    int t = threadIdx.x;
    int i = blockIdx.x * SCAN_BLK + t;
    int val = (i < n) ? cnt[i] : 0;
    s[t] = val;
    __syncthreads();
    for (int off = 1; off < SCAN_BLK; off <<= 1) {
        int x = (t >= off) ? s[t - off] : 0;
        __syncthreads();
        s[t] += x;
        __syncthreads();
    }
    if (i < n) rowptr[i + 1] = s[t];
    if (t == SCAN_BLK - 1) bsums[blockIdx.x] = s[t];
}

// scan step 2: exclusive scan of block sums (single thread; nb ~ 98)
__global__ void scan2(int* bsums, int nb) {
    if (threadIdx.x == 0 && blockIdx.x == 0) {
        int run = 0;
        for (int b = 0; b < nb; ++b) { int v = bsums[b]; bsums[b] = run; run += v; }
    }
}

// scan step 3: add block offsets, init cursor
__global__ void scan3(int* __restrict__ rowptr, int* __restrict__ cursor,
                      const int* __restrict__ bsums, int n) {
    int i = blockIdx.x * blockDim.x + threadIdx.x;
    if (i == 0) { rowptr[0] = 0; cursor[0] = 0; }
    if (i < n) {
        int v = rowptr[i + 1] + bsums[i / SCAN_BLK];
        rowptr[i + 1] = v;
        cursor[i + 1] = v;
    }
}

__global__ void scatter_csr(const void* ei, int* __restrict__ cursor,
                            int* __restrict__ csr, int E) {
    int e = blockIdx.x * blockDim.x + threadIdx.x;
    if (e >= E) return;
    bool is64 = edges_are_i64(ei);
    int s = edge_at(ei, is64, e);
    int d = edge_at(ei, is64, E + e);
    int pos = atomicAdd(&cursor[d], 1);
    csr[pos] = s;
}

// ---------------------------------------------------------------------------
// GEMM: Y[N,64] = (X[N,81] @ W[81,64]) * dis[n]
__global__ void gemm81_dis(const float* __restrict__ X, const float* __restrict__ W,
                           const float* __restrict__ dis, float* __restrict__ Y, int N) {
    __shared__ float Ws[IND * HID];
    __shared__ float Xs[16][IND];
    int tx = threadIdx.x;  // 0..63
    int ty = threadIdx.y;  // 0..3
    int tid = ty * 64 + tx;
    for (int i = tid; i < IND * HID; i += 256) Ws[i] = W[i];
    int n0 = blockIdx.x * 16;
    for (int i = tid; i < 16 * IND; i += 256) {
        int r = i / IND, c = i % IND;
        int n = n0 + r;
        Xs[r][c] = (n < N) ? X[n * IND + c] : 0.0f;
    }
    __syncthreads();
    float acc[4] = {0.f, 0.f, 0.f, 0.f};
    for (int k = 0; k < IND; ++k) {
        float w = Ws[k * HID + tx];
        #pragma unroll
        for (int r = 0; r < 4; ++r) acc[r] += Xs[ty * 4 + r][k] * w;
    }
    #pragma unroll
    for (int r = 0; r < 4; ++r) {
        int n = n0 + ty * 4 + r;
        if (n < N) Y[n * HID + tx] = acc[r] * dis[n];
    }
}

// GEMM with fused BN+ReLU input transform: Y = (relu(bn(X)) @ W) * dis[n]
__global__ void gemm64_bn_dis(const float* __restrict__ X, const float* __restrict__ W,
                              const float* __restrict__ stats, const float* __restrict__ dis,
                              float* __restrict__ Y, int N) {
    __shared__ float Ws[HID * HID];
    __shared__ float Xs[16][HID];
    __shared__ float sc[64], sh[64];
    int tx = threadIdx.x;
    int ty = threadIdx.y;
    int tid = ty * 64 + tx;
    for (int i = tid; i < HID * HID; i += 256) Ws[i] = W[i];
    if (tid < 64) { sc[tid] = stats[tid]; sh[tid] = stats[64 + tid]; }
    int n0 = blockIdx.x * 16;
    __syncthreads();
    for (int i = tid; i < 16 * HID; i += 256) {
        int r = i >> 6, c = i & 63;
        int n = n0 + r;
        float raw = (n < N) ? X[n * HID + c] : 0.0f;
        Xs[r][c] = fmaxf(fmaf(raw, sc[c], sh[c]), 0.0f);
    }
    __syncthreads();
    float acc[4] = {0.f, 0.f, 0.f, 0.f};
    for (int k = 0; k < HID; ++k) {
        float w = Ws[k * HID + tx];
        #pragma unroll
        for (int r = 0; r < 4; ++r) acc[r] += Xs[ty * 4 + r][k] * w;
    }
    #pragma unroll
    for (int r = 0; r < 4; ++r) {
        int n = n0 + ty * 4 + r;
        if (n < N) Y[n * HID + tx] = acc[r] * dis[n];
    }
}

// Final heads: mu = X@Wmu + bmu ; ls = X@Wls + bls  (X already fully aggregated)
__global__ void gemm_mu_ls(const float* __restrict__ X,
                           const float* __restrict__ Wmu, const float* __restrict__ bmu,
                           const float* __restrict__ Wls, const float* __restrict__ bls,
                           float* __restrict__ out, int N) {
    __shared__ float Ws[HID * 64];
    __shared__ float bs[64];
    __shared__ float Xs[16][HID];
    int tx = threadIdx.x;
    int ty = threadIdx.y;
    int tid = ty * 64 + tx;
    for (int i = tid; i < HID * 64; i += 256) {
        int k = i >> 6, f = i & 63;
        Ws[i] = (f < LAT) ? Wmu[k * LAT + f] : Wls[k * LAT + (f - LAT)];
    }
    if (tid < 64) bs[tid] = (tid < LAT) ? bmu[tid] : bls[tid - LAT];
    int n0 = blockIdx.x * 16;
    for (int i = tid; i < 16 * HID; i += 256) {
        int r = i >> 6, c = i & 63;
        int n = n0 + r;
        Xs[r][c] = (n < N) ? X[n * HID + c] : 0.0f;
    }
    __syncthreads();
    float acc[4] = {0.f, 0.f, 0.f, 0.f};
    for (int k = 0; k < HID; ++k) {
        float w = Ws[k * 64 + tx];
        #pragma unroll
        for (int r = 0; r < 4; ++r) acc[r] += Xs[ty * 4 + r][k] * w;
    }
    int f = tx & (LAT - 1);
    long long off = (tx < LAT) ? 0 : (long long)N * LAT;
    #pragma unroll
    for (int r = 0; r < 4; ++r) {
        int n = n0 + ty * 4 + r;
        if (n < N) out[off + (long long)n * LAT + f] = acc[r] + bs[tx];
    }
}

// ---------------------------------------------------------------------------
// Aggregation (gather): out[n] = (sum_{s in nbr(n)} Hs[s] + Hs[n]) * dis[n] + b
// Hs rows are pre-scaled by dis[src]. One warp per node, float2 per lane.
__global__ void aggregate(const float2* __restrict__ H2, const int* __restrict__ rowptr,
                          const int* __restrict__ csr, const float* __restrict__ dis,
                          const float* __restrict__ bias, float2* __restrict__ out2, int N) {
    int n = (blockIdx.x * blockDim.x + threadIdx.x) >> 5;
    int lane = threadIdx.x & 31;
    if (n >= N) return;
    size_t base = (size_t)n * 32 + lane;
    float2 acc = __ldg(&H2[base]);          // self term (Hs[n]); *dis[n] applied at end
    int row = rowptr[n], end = rowptr[n + 1];
    for (int j0 = row; j0 < end; j0 += 32) {
        int m = end - j0; if (m > 32) m = 32;
        int myIdx = (lane < m) ? csr[j0 + lane] : 0;
        for (int t = 0; t < m; ++t) {
            int s = __shfl_sync(0xffffffffu, myIdx, t);
            float2 v = __ldg(&H2[(size_t)s * 32 + lane]);
            acc.x += v.x; acc.y += v.y;
        }
    }
    float dd = dis[n];
    float bx = 0.f, by = 0.f;
    if (bias) { float2 b = ((const float2*)bias)[lane]; bx = b.x; by = b.y; }
    out2[base] = make_float2(fmaf(acc.x, dd, bx), fmaf(acc.y, dd, by));
}

// ---------------------------------------------------------------------------
// BatchNorm
__global__ void zero_stats(float* stats) {
    int i = threadIdx.x;
    if (i < 128) stats[i] = 0.0f;
}

__global__ void bn_stats(const float* __restrict__ H, float* stats, int N) {
    int tid = threadIdx.x;
    int col = tid & 63;
    int r = blockIdx.x * 4 + (tid >> 6);
    int rstride = gridDim.x * 4;
    float s = 0.0f, q = 0.0f;
    for (; r < N; r += rstride) {
        float v = H[r * HID + col];
        s += v; q += v * v;
    }
    __shared__ float sh[256], qh[256];
    sh[tid] = s; qh[tid] = q;
    __syncthreads();
    if (tid < 64) {
        float S = sh[tid] + sh[tid + 64] + sh[tid + 128] + sh[tid + 192];
        float Q = qh[tid] + qh[tid + 64] + qh[tid + 128] + qh[tid + 192];
        atomicAdd(&stats[tid], S);
        atomicAdd(&stats[64 + tid], Q);
    }
}

__global__ void bn_finalize(float* stats, const float* __restrict__ g,
                            const float* __restrict__ beta, int N) {
    int f = threadIdx.x;
    if (f >= 64) return;
    float invN = 1.0f / (float)N;
    float m = stats[f] * invN;
    float v = stats[64 + f] * invN - m * m;
    float scale = g[f] * rsqrtf(v + BN_EPS);
    stats[f] = scale;
    stats[64 + f] = beta[f] - m * scale;
}

// A[n,f] = relu(bn(B[n,f])) * dis[n]   (materialize Hs for the shared head agg)
__global__ void bn_relu_dis(const float* __restrict__ H, const float* __restrict__ stats,
                            const float* __restrict__ dis, float* __restrict__ out, int total) {
    int idx = blockIdx.x * blockDim.x + threadIdx.x;
    if (idx >= total) return;
    int f = idx & 63;
    int n = idx >> 6;
    float y = fmaxf(fmaf(H[idx], stats[f], stats[64 + f]), 0.0f);
    out[idx] = y * dis[n];
}

// ---------------------------------------------------------------------------
extern "C" void kernel_launch(void* const* d_in, const int* in_sizes, int n_in,
                              void* d_out, int out_size) {
    const float* x    = (const float*)d_in[0];
    const void*  ei   = d_in[1];
    const float* W1   = (const float*)d_in[2];
    const float* b1   = (const float*)d_in[3];
    const float* g1   = (const float*)d_in[4];
    const float* be1  = (const float*)d_in[5];
    const float* W2   = (const float*)d_in[6];
    const float* b2   = (const float*)d_in[7];
    const float* g2   = (const float*)d_in[8];
    const float* be2  = (const float*)d_in[9];
    const float* Wmu  = (const float*)d_in[10];
    const float* bmu  = (const float*)d_in[11];
    const float* Wls  = (const float*)d_in[12];
    const float* bls  = (const float*)d_in[13];
    float* out = (float*)d_out;

    int N = in_sizes[0] / IND;
    int E = in_sizes[1] / 2;

    float *pA, *pB, *pDis, *pStats;
    int *pCnt, *pRow, *pCur, *pCsr, *pBs;
    cudaGetSymbolAddress((void**)&pA, g_bufA);
    cudaGetSymbolAddress((void**)&pB, g_bufB);
    cudaGetSymbolAddress((void**)&pDis, g_dis);
    cudaGetSymbolAddress((void**)&pStats, g_stats);
    cudaGetSymbolAddress((void**)&pCnt, g_cnt);
    cudaGetSymbolAddress((void**)&pRow, g_rowptr);
    cudaGetSymbolAddress((void**)&pCur, g_cursor);
    cudaGetSymbolAddress((void**)&pCsr, g_csr);
    cudaGetSymbolAddress((void**)&pBs, g_bsums);

    int NH = N * HID;
    int nScanBlocks = (N + SCAN_BLK - 1) / SCAN_BLK;
    dim3 gThr(64, 4);
    int gemmGrid = (N + 15) / 16;
    int aggGrid = (N * 32 + 255) / 256;   // 8 warps/block, warp per node

    // 1. CSR build + normalization
    zero_cnt<<<(N + 255) / 256, 256>>>(pCnt, N);
    hist_dst<<<(E + 255) / 256, 256>>>(ei, pCnt, E);
    scan1<<<nScanBlocks, SCAN_BLK>>>(pCnt, pRow, pBs, N);
    scan2<<<1, 32>>>(pBs, nScanBlocks);
    scan3<<<(N + 255) / 256, 256>>>(pRow, pCur, pBs, N);
    dis_from_cnt<<<(N + 255) / 256, 256>>>(pCnt, pDis, N);
    scatter_csr<<<(E + 255) / 256, 256>>>(ei, pCur, pCsr, E);

    // 2. conv1
    gemm81_dis<<<gemmGrid, gThr>>>(x, W1, pDis, pA, N);
    aggregate<<<aggGrid, 256>>>((const float2*)pA, pRow, pCsr, pDis, b1, (float2*)pB, N);

    // 3. BN1 stats
    zero_stats<<<1, 128>>>(pStats);
    bn_stats<<<512, 256>>>(pB, pStats, N);
    bn_finalize<<<1, 64>>>(pStats, g1, be1, N);

    // 4. conv2 (BN+ReLU fused into GEMM input)
    gemm64_bn_dis<<<gemmGrid, gThr>>>(pB, W2, pStats, pDis, pA, N);
    aggregate<<<aggGrid, 256>>>((const float2*)pA, pRow, pCsr, pDis, b2, (float2*)pB, N);

    // 5. BN2 stats
    zero_stats<<<1, 128>>>(pStats);
    bn_stats<<<512, 256>>>(pB, pStats, N);
    bn_finalize<<<1, 64>>>(pStats, g2, be2, N);

    // 6. h = relu(bn(B)) * dis ; shared aggregation for both heads
    bn_relu_dis<<<(NH + 255) / 256, 256>>>(pB, pStats, pDis, pA, NH);
    aggregate<<<aggGrid, 256>>>((const float2*)pA, pRow, pCsr, pDis, (const float*)nullptr, (float2*)pB, N);

    // 7. heads
    gemm_mu_ls<<<gemmGrid, gThr>>>(pB, Wmu, bmu, Wls, bls, out, N);
}

// round 3
// speedup vs baseline: 4.7908x; 1.0977x over previous
#include <cuda_runtime.h>
#include <cuda_fp16.h>
#include <cuda_bf16.h>

#define NN 100000
#define EE 3200000
#define IND 81
#define HID 64
#define LAT 32
#define BN_EPS 1e-5f
#define SCAN_BLK 1024

// Scratch (device globals; no allocation allowed)
__device__ __align__(128) __half2 g_half[NN * 32];   // fp16 Hs rows (64 feats = 32 half2)
__device__ float g_bufA[NN * HID];
__device__ float g_bufB[NN * HID];
__device__ float g_dis[NN];
__device__ int   g_cnt[NN];
__device__ int   g_rowptr[NN + 1];
__device__ int   g_cursor[NN + 1];
__device__ int   g_csr[EE];
__device__ int   g_bsums[(NN + SCAN_BLK - 1) / SCAN_BLK + 1];
__device__ float g_stats[128];   // sum[64], sumsq[64] -> scale[64], shift[64]

// ---------------------------------------------------------------------------
__device__ __forceinline__ bool edges_are_i64(const void* ei) {
    long long v0 = ((const long long*)ei)[0];
    return (v0 >= 0 && v0 < 1000000LL);
}
__device__ __forceinline__ int edge_at(const void* ei, bool is64, int i) {
    return is64 ? (int)((const long long*)ei)[i] : ((const int*)ei)[i];
}

// ---------------------------------------------------------------------------
__global__ void zero_cnt(int* cnt, int n) {
    int i = blockIdx.x * blockDim.x + threadIdx.x;
    if (i < n) cnt[i] = 0;
}

__global__ void hist_dst(const void* ei, int* cnt, int E) {
    int e = blockIdx.x * blockDim.x + threadIdx.x;
    if (e >= E) return;
    bool is64 = edges_are_i64(ei);
    int d = edge_at(ei, is64, E + e);
    atomicAdd(&cnt[d], 1);
}

// scan step 1: per-block inclusive scan of cnt, write rowptr[i+1], block sums
__global__ void scan1(const int* __restrict__ cnt, int* __restrict__ rowptr,
                      int* __restrict__ bsums, int n) {
    __shared__ int s[SCAN_BLK];
    int t = threadIdx.x;
    int i = blockIdx.x * SCAN_BLK + t;
    int val = (i < n) ? cnt[i] : 0;
    s[t] = val;
    __syncthreads();
    for (int off = 1; off < SCAN_BLK; off <<= 1) {
        int x = (t >= off) ? s[t - off] : 0;
        __syncthreads();
        s[t] += x;
        __syncthreads();
    }
    if (i < n) rowptr[i + 1] = s[t];
    if (t == SCAN_BLK - 1) bsums[blockIdx.x] = s[t];
}

// scan step 2: exclusive scan of block sums (parallel, nb <= 1024)
__global__ void scan2(int* bsums, int nb) {
    __shared__ int s[SCAN_BLK];
    int t = threadIdx.x;
    int v = (t < nb) ? bsums[t] : 0;
    s[t] = v;
    __syncthreads();
    for (int off = 1; off < SCAN_BLK; off <<= 1) {
        int x = (t >= off) ? s[t - off] : 0;
        __syncthreads();
        s[t] += x;
        __syncthreads();
    }
    if (t < nb) bsums[t] = s[t] - v;   // exclusive
}

// scan step 3: add block offsets, init cursor, compute dis = rsqrt(deg+1)
__global__ void scan3(int* __restrict__ rowptr, int* __restrict__ cursor,
                      const int* __restrict__ bsums, const int* __restrict__ cnt,
                      float* __restrict__ dis, int n) {
    int i = blockIdx.x * blockDim.x + threadIdx.x;
    if (i == 0) { rowptr[0] = 0; cursor[0] = 0; }
    if (i < n) {
        int v = rowptr[i + 1] + bsums[i / SCAN_BLK];
        rowptr[i + 1] = v;
        cursor[i + 1] = v;
        dis[i] = rsqrtf((float)(cnt[i] + 1));
    }
}

__global__ void scatter_csr(const void* ei, int* __restrict__ cursor,
                            int* __restrict__ csr, int E) {
    int e = blockIdx.x * blockDim.x + threadIdx.x;
    if (e >= E) return;
    bool is64 = edges_are_i64(ei);
    int s = edge_at(ei, is64, e);
    int d = edge_at(ei, is64, E + e);
    int pos = atomicAdd(&cursor[d], 1);
    csr[pos] = s;
}

// ---------------------------------------------------------------------------
// GEMM: Yh[N,64] = half((X[N,81] @ W[81,64]) * dis[n])
__global__ void gemm81_dis(const float* __restrict__ X, const float* __restrict__ W,
                           const float* __restrict__ dis, __half* __restrict__ Yh, int N) {
    __shared__ float Ws[IND * HID];
    __shared__ float Xs[16][IND];
    int tx = threadIdx.x;  // 0..63
    int ty = threadIdx.y;  // 0..3
    int tid = ty * 64 + tx;
    for (int i = tid; i < IND * HID; i += 256) Ws[i] = W[i];
    int n0 = blockIdx.x * 16;
    for (int i = tid; i < 16 * IND; i += 256) {
        int r = i / IND, c = i % IND;
        int n = n0 + r;
        Xs[r][c] = (n < N) ? X[n * IND + c] : 0.0f;
    }
    __syncthreads();
    float acc[4] = {0.f, 0.f, 0.f, 0.f};
    for (int k = 0; k < IND; ++k) {
        float w = Ws[k * HID + tx];
        #pragma unroll
        for (int r = 0; r < 4; ++r) acc[r] += Xs[ty * 4 + r][k] * w;
    }
    #pragma unroll
    for (int r = 0; r < 4; ++r) {
        int n = n0 + ty * 4 + r;
        if (n < N) Yh[n * HID + tx] = __float2half(acc[r] * dis[n]);
    }
}

// GEMM with fused BN+ReLU input transform: Yh = half((relu(bn(X)) @ W) * dis[n])
__global__ void gemm64_bn_dis(const float* __restrict__ X, const float* __restrict__ W,
                              const float* __restrict__ stats, const float* __restrict__ dis,
                              __half* __restrict__ Yh, int N) {
    __shared__ float Ws[HID * HID];
    __shared__ float Xs[16][HID];
    __shared__ float sc[64], sh[64];
    int tx = threadIdx.x;
    int ty = threadIdx.y;
    int tid = ty * 64 + tx;
    for (int i = tid; i < HID * HID; i += 256) Ws[i] = W[i];
    if (tid < 64) { sc[tid] = stats[tid]; sh[tid] = stats[64 + tid]; }
    int n0 = blockIdx.x * 16;
    __syncthreads();
    for (int i = tid; i < 16 * HID; i += 256) {
        int r = i >> 6, c = i & 63;
        int n = n0 + r;
        float raw = (n < N) ? X[n * HID + c] : 0.0f;
        Xs[r][c] = fmaxf(fmaf(raw, sc[c], sh[c]), 0.0f);
    }
    __syncthreads();
    float acc[4] = {0.f, 0.f, 0.f, 0.f};
    for (int k = 0; k < HID; ++k) {
        float w = Ws[k * HID + tx];
        #pragma unroll
        for (int r = 0; r < 4; ++r) acc[r] += Xs[ty * 4 + r][k] * w;
    }
    #pragma unroll
    for (int r = 0; r < 4; ++r) {
        int n = n0 + ty * 4 + r;
        if (n < N) Yh[n * HID + tx] = __float2half(acc[r] * dis[n]);
    }
}

// Final heads: mu = X@Wmu + bmu ; ls = X@Wls + bls  (X fully aggregated, fp32)
__global__ void gemm_mu_ls(const float* __restrict__ X,
                           const float* __restrict__ Wmu, const float* __restrict__ bmu,
                           const float* __restrict__ Wls, const float* __restrict__ bls,
                           float* __restrict__ out, int N) {
    __shared__ float Ws[HID * 64];
    __shared__ float bs[64];
    __shared__ float Xs[16][HID];
    int tx = threadIdx.x;
    int ty = threadIdx.y;
    int tid = ty * 64 + tx;
    for (int i = tid; i < HID * 64; i += 256) {
        int k = i >> 6, f = i & 63;
        Ws[i] = (f < LAT) ? Wmu[k * LAT + f] : Wls[k * LAT + (f - LAT)];
    }
    if (tid < 64) bs[tid] = (tid < LAT) ? bmu[tid] : bls[tid - LAT];
    int n0 = blockIdx.x * 16;
    for (int i = tid; i < 16 * HID; i += 256) {
        int r = i >> 6, c = i & 63;
        int n = n0 + r;
        Xs[r][c] = (n < N) ? X[n * HID + c] : 0.0f;
    }
    __syncthreads();
    float acc[4] = {0.f, 0.f, 0.f, 0.f};
    for (int k = 0; k < HID; ++k) {
        float w = Ws[k * 64 + tx];
        #pragma unroll
        for (int r = 0; r < 4; ++r) acc[r] += Xs[ty * 4 + r][k] * w;
    }
    int f = tx & (LAT - 1);
    long long off = (tx < LAT) ? 0 : (long long)N * LAT;
    #pragma unroll
    for (int r = 0; r < 4; ++r) {
        int n = n0 + ty * 4 + r;
        if (n < N) out[off + (long long)n * LAT + f] = acc[r] + bs[tx];
    }
}

// ---------------------------------------------------------------------------
// Aggregation (gather): out[n] = (sum_{s in nbr(n)} Hs[s] + Hs[n]) * dis[n] + b
// Hs rows fp16, pre-scaled by dis[src]. Warp per node; 1 half2 (2 feats) per lane.
// Neighbor index via warp-uniform broadcast LDG (no shfl chain).
__global__ void aggregate_h(const __half2* __restrict__ Hh, const int* __restrict__ rowptr,
                            const int* __restrict__ csr, const float* __restrict__ dis,
                            const float* __restrict__ bias, float2* __restrict__ out2, int N) {
    int n = (blockIdx.x * blockDim.x + threadIdx.x) >> 5;
    int lane = threadIdx.x & 31;
    if (n >= N) return;
    int base = n * 32 + lane;
    float2 a0 = __half22float2(__ldg(&Hh[base]));   // self term
    float2 a1 = make_float2(0.f, 0.f);
    int j = rowptr[n], end = rowptr[n + 1];
    for (; j + 2 <= end; j += 2) {
        int s0 = __ldg(&csr[j]);
        int s1 = __ldg(&csr[j + 1]);
        float2 v0 = __half22float2(__ldg(&Hh[s0 * 32 + lane]));
        float2 v1 = __half22float2(__ldg(&Hh[s1 * 32 + lane]));
        a0.x += v0.x; a0.y += v0.y;
        a1.x += v1.x; a1.y += v1.y;
    }
    if (j < end) {
        int s0 = __ldg(&csr[j]);
        float2 v0 = __half22float2(__ldg(&Hh[s0 * 32 + lane]));
        a0.x += v0.x; a0.y += v0.y;
    }
    float dd = dis[n];
    float bx = 0.f, by = 0.f;
    if (bias) { float2 b = ((const float2*)bias)[lane]; bx = b.x; by = b.y; }
    out2[base] = make_float2(fmaf(a0.x + a1.x, dd, bx), fmaf(a0.y + a1.y, dd, by));
}

// ---------------------------------------------------------------------------
// BatchNorm
__global__ void zero_stats(float* stats) {
    int i = threadIdx.x;
    if (i < 128) stats[i] = 0.0f;
}

__global__ void bn_stats(const float* __restrict__ H, float* stats, int N) {
    int tid = threadIdx.x;
    int col = tid & 63;
    int r = blockIdx.x * 4 + (tid >> 6);
    int rstride = gridDim.x * 4;
    float s = 0.0f, q = 0.0f;
    for (; r < N; r += rstride) {
        float v = H[r * HID + col];
        s += v; q += v * v;
    }
    __shared__ float sh[256], qh[256];
    sh[tid] = s; qh[tid] = q;
    __syncthreads();
    if (tid < 64) {
        float S = sh[tid] + sh[tid + 64] + sh[tid + 128] + sh[tid + 192];
        float Q = qh[tid] + qh[tid + 64] + qh[tid + 128] + qh[tid + 192];
        atomicAdd(&stats[tid], S);
        atomicAdd(&stats[64 + tid], Q);
    }
}

__global__ void bn_finalize(float* stats, const float* __restrict__ g,
                            const float* __restrict__ beta, int N) {
    int f = threadIdx.x;
    if (f >= 64) return;
    float invN = 1.0f / (float)N;
    float m = stats[f] * invN;
    float v = stats[64 + f] * invN - m * m;
    float scale = g[f] * rsqrtf(v + BN_EPS);
    stats[f] = scale;
    stats[64 + f] = beta[f] - m * scale;
}

// Hs[n,f] = half(relu(bn(B[n,f])) * dis[n])
__global__ void bn_relu_dis(const float* __restrict__ H, const float* __restrict__ stats,
                            const float* __restrict__ dis, __half* __restrict__ out, int total) {
    int idx = blockIdx.x * blockDim.x + threadIdx.x;
    if (idx >= total) return;
    int f = idx & 63;
    int n = idx >> 6;
    float y = fmaxf(fmaf(H[idx], stats[f], stats[64 + f]), 0.0f);
    out[idx] = __float2half(y * dis[n]);
}

// ---------------------------------------------------------------------------
extern "C" void kernel_launch(void* const* d_in, const int* in_sizes, int n_in,
                              void* d_out, int out_size) {
    const float* x    = (const float*)d_in[0];
    const void*  ei   = d_in[1];
    const float* W1   = (const float*)d_in[2];
    const float* b1   = (const float*)d_in[3];
    const float* g1   = (const float*)d_in[4];
    const float* be1  = (const float*)d_in[5];
    const float* W2   = (const float*)d_in[6];
    const float* b2   = (const float*)d_in[7];
    const float* g2   = (const float*)d_in[8];
    const float* be2  = (const float*)d_in[9];
    const float* Wmu  = (const float*)d_in[10];
    const float* bmu  = (const float*)d_in[11];
    const float* Wls  = (const float*)d_in[12];
    const float* bls  = (const float*)d_in[13];
    float* out = (float*)d_out;

    int N = in_sizes[0] / IND;
    int E = in_sizes[1] / 2;

    float *pA, *pB, *pDis, *pStats;
    __half2* pH;
    int *pCnt, *pRow, *pCur, *pCsr, *pBs;
    cudaGetSymbolAddress((void**)&pA, g_bufA);
    cudaGetSymbolAddress((void**)&pB, g_bufB);
    cudaGetSymbolAddress((void**)&pDis, g_dis);
    cudaGetSymbolAddress((void**)&pStats, g_stats);
    cudaGetSymbolAddress((void**)&pH, g_half);
    cudaGetSymbolAddress((void**)&pCnt, g_cnt);
    cudaGetSymbolAddress((void**)&pRow, g_rowptr);
    cudaGetSymbolAddress((void**)&pCur, g_cursor);
    cudaGetSymbolAddress((void**)&pCsr, g_csr);
    cudaGetSymbolAddress((void**)&pBs, g_bsums);

    int NH = N * HID;
    int nScanBlocks = (N + SCAN_BLK - 1) / SCAN_BLK;
    dim3 gThr(64, 4);
    int gemmGrid = (N + 15) / 16;
    int aggGrid = (N * 32 + 255) / 256;   // warp per node

    // 1. CSR build + normalization
    zero_cnt<<<(N + 255) / 256, 256>>>(pCnt, N);
    hist_dst<<<(E + 255) / 256, 256>>>(ei, pCnt, E);
    scan1<<<nScanBlocks, SCAN_BLK>>>(pCnt, pRow, pBs, N);
    scan2<<<1, SCAN_BLK>>>(pBs, nScanBlocks);
    scan3<<<(N + 255) / 256, 256>>>(pRow, pCur, pBs, pCnt, pDis, N);
    scatter_csr<<<(E + 255) / 256, 256>>>(ei, pCur, pCsr, E);

    // 2. conv1
    gemm81_dis<<<gemmGrid, gThr>>>(x, W1, pDis, (__half*)pH, N);
    aggregate_h<<<aggGrid, 256>>>(pH, pRow, pCsr, pDis, b1, (float2*)pB, N);

    // 3. BN1 stats
    zero_stats<<<1, 128>>>(pStats);
    bn_stats<<<512, 256>>>(pB, pStats, N);
    bn_finalize<<<1, 64>>>(pStats, g1, be1, N);

    // 4. conv2 (BN+ReLU fused into GEMM input)
    gemm64_bn_dis<<<gemmGrid, gThr>>>(pB, W2, pStats, pDis, (__half*)pH, N);
    aggregate_h<<<aggGrid, 256>>>(pH, pRow, pCsr, pDis, b2, (float2*)pB, N);

    // 5. BN2 stats
    zero_stats<<<1, 128>>>(pStats);
    bn_stats<<<512, 256>>>(pB, pStats, N);
    bn_finalize<<<1, 64>>>(pStats, g2, be2, N);

    // 6. Hs = relu(bn(B)) * dis ; shared aggregation for both heads
    bn_relu_dis<<<(NH + 255) / 256, 256>>>(pB, pStats, pDis, (__half*)pH, NH);
    aggregate_h<<<aggGrid, 256>>>(pH, pRow, pCsr, pDis, (const float*)nullptr, (float2*)pA, N);

    // 7. heads
    gemm_mu_ls<<<gemmGrid, gThr>>>(pA, Wmu, bmu, Wls, bls, out, N);
}